// round 8
// baseline (speedup 1.0000x reference)
#include <cuda_runtime.h>
#include <cstdint>

// SlidingWindowCmn (16, 60000, 80) fp32, window=600, min=100, center=False,
// norm_vars=True.
// Distributed 16B cp.async -> 672-row SMEM ring (+8 mirror) -> per-thread
// sliding window (1 thread/feature). Outputs staged in SMEM (STS) and
// flushed with TMA bulk stores (cp.async.bulk) instead of per-thread STG,
// removing ~200 LSU cycles per 16-row group. Lead = 3 groups (48 rows):
// cross-thread overwrite safety: 16*lead + 15 < 672 - 601 = 71.

namespace {
constexpr int kB      = 16;
constexpr int kT      = 60000;
constexpr int kF      = 80;
constexpr int kWin    = 600;
constexpr int kMin    = 100;
constexpr int kChunks = 9;
constexpr int kL      = 6672;                 // 8*6672 + 6624 = 60000
constexpr int kRL     = 672;                  // logical ring rows
constexpr int kRLf    = kRL * kF;             // 53760 floats
constexpr uint32_t kRLb = kRL * 320u;         // 215040 bytes (logical)
constexpr int kMirF   = 8 * kF;               // 8 mirror rows
constexpr int kStageF = 16 * kF;              // 1280 floats per stage buffer
constexpr int kRingTotF = kRLf + kMirF;       // 54400 floats
constexpr uint32_t kSmemB = (uint32_t)(kRingTotF + 2 * kStageF) * 4u; // 227840
constexpr int kVO     = kRL - kWin - 1;       // 71 rows vn->vo distance
constexpr float kInvW = 1.0f / 601.0f;
constexpr int kGrid   = kB * kChunks;         // 144
}

__device__ __forceinline__ uint32_t smem_u32(const void* p) {
    uint32_t a;
    asm("{ .reg .u64 t; cvta.to.shared.u64 t, %1; cvt.u32.u64 %0, t; }"
        : "=r"(a) : "l"(p));
    return a;
}
__device__ __forceinline__ void cpa16(uint32_t s, const float* g) {
    asm volatile("cp.async.cg.shared.global [%0], [%1], 16;" :: "r"(s), "l"(g));
}
__device__ __forceinline__ void cpcommit() {
    asm volatile("cp.async.commit_group;" ::: "memory");
}
__device__ __forceinline__ void cpwait2() {
    asm volatile("cp.async.wait_group 2;" ::: "memory");
}
__device__ __forceinline__ void fence_pa() {
    asm volatile("fence.proxy.async.shared::cta;" ::: "memory");
}
__device__ __forceinline__ void bulk_store(float* g, uint32_t s) {
    asm volatile("cp.async.bulk.global.shared::cta.bulk_group [%0], [%1], %2;"
                 :: "l"(g), "r"(s), "r"(5120) : "memory");
}
__device__ __forceinline__ void bulk_commit() {
    asm volatile("cp.async.bulk.commit_group;" ::: "memory");
}
__device__ __forceinline__ void bulk_waitread0() {
    asm volatile("cp.async.bulk.wait_group.read 0;" ::: "memory");
}

__global__ void __launch_bounds__(kF, 1)
cmn_kernel(const float* __restrict__ x, float* __restrict__ out)
{
    extern __shared__ float smem[];
    float* ring  = smem;
    float* stage = smem + kRingTotF;

    const int f = threadIdx.x;                    // feature 0..79
    const int c = blockIdx.x % kChunks;
    const int b = blockIdx.x / kChunks;

    const float* xb = x + (size_t)b * kT * kF;
    const int start = c * kL;
    const int end   = (c == kChunks - 1) ? kT : start + kL;

    const uint32_t rsb = smem_u32(ring);
    const uint32_t stb = smem_u32(stage);
    const float* pClamp = x + ((size_t)kB * kT - 16) * kF;

    int vnF;                  // consume group float-offset (slot*80)
    uint32_t issB;            // issue group byte-offset
    const float* pIss;
    if (c == 0) {
        vnF = 0; issB = 0; pIss = xb;
    } else {
        const int t0   = start - 608;             // 16-aligned: 7 pad + 601 warmup
        const int slot = t0 % kRL;                // multiple of 16
        vnF = slot * kF; issB = (uint32_t)slot * 320u;
        pIss = xb + (size_t)t0 * kF;
    }

    auto issue16 = [&]() {
        const float* q  = (pIss > pClamp) ? pClamp : pIss;
        const float* qt = q + f * 4;                         // 16B per thread
        const uint32_t a = rsb + issB + (uint32_t)(f << 4);
        cpa16(a,         qt);
        cpa16(a + 1280u, qt + 320);
        cpa16(a + 2560u, qt + 640);
        cpa16(a + 3840u, qt + 960);
        if (issB == 0) {                          // wrap group: mirror rows 0..7
            const uint32_t m = rsb + kRLb + (uint32_t)(f << 4);
            cpa16(m,         qt);
            cpa16(m + 1280u, qt + 320);
        }
        cpcommit();
        pIss += 16 * kF;
        issB += 5120u; if (issB == kRLb) issB = 0;
    };

    // prologue: 3 groups (48 rows) in flight
    issue16(); issue16(); issue16();

    float s = 0.f, ss = 0.f, mean = 0.f, qss = 0.f;
    float* po = out + (size_t)b * kT * kF + f;
    int nSteady, g0row;

    if (c == 0) {
        // groups 0..5: rows 0..95 accumulate
        #pragma unroll 1
        for (int g = 0; g < 6; ++g) {
            cpwait2(); __syncthreads();
            const float* rv = ring + vnF + f;
            #pragma unroll
            for (int u = 0; u < 16; ++u) {
                float v = rv[u * kF]; s += v; ss = __fmaf_rn(v, v, ss);
            }
            vnF += 16 * kF; issue16();
        }
        // group 6: rows 96..111
        {
            cpwait2(); __syncthreads();
            const float* rv = ring + vnF + f;
            #pragma unroll
            for (int u = 0; u < 4; ++u) {          // rows 96..99
                float v = rv[u * kF]; s += v; ss = __fmaf_rn(v, v, ss);
            }
            const float inv = 1.0f / (float)kMin;  // burst rows 0..99
            const float m0  = s * inv;
            const float vr0 = __fmaf_rn(-m0, m0, ss * inv);
            const float rs0 = rsqrtf(vr0);
            #pragma unroll 4
            for (int t = 0; t < kMin; ++t) {
                float v = ring[t * kF + f];
                __stcs(po + t * kF, (v - m0) * rs0);
            }
            float n = 100.0f;
            #pragma unroll
            for (int u = 4; u < 16; ++u) {         // rows 100..111 growing
                float v = rv[u * kF]; s += v; ss = __fmaf_rn(v, v, ss);
                n += 1.0f;
                float inv2 = __fdividef(1.0f, n);
                float m    = s * inv2;
                float var  = __fmaf_rn(-m, m, ss * inv2);
                __stcs(po + (96 + u) * kF, (v - m) * rsqrtf(var));
            }
            vnF += 16 * kF; issue16();
        }
        // groups 7..36: rows 112..591 growing
        po += 112 * kF;
        float n = 112.0f;
        #pragma unroll 1
        for (int g = 7; g < 37; ++g) {
            cpwait2(); __syncthreads();
            const float* rv = ring + vnF + f;
            #pragma unroll
            for (int u = 0; u < 16; ++u) {
                float v = rv[u * kF]; s += v; ss = __fmaf_rn(v, v, ss);
                n += 1.0f;
                float inv = __fdividef(1.0f, n);
                float m   = s * inv;
                float var = __fmaf_rn(-m, m, ss * inv);
                __stcs(po + u * kF, (v - m) * rsqrtf(var));
            }
            vnF += 16 * kF; po += 16 * kF; issue16();
        }
        // group 37: rows 592..607 (transition at t=600)
        {
            cpwait2(); __syncthreads();
            const float* rv = ring + vnF + f;
            #pragma unroll
            for (int u = 0; u < 8; ++u) {          // rows 592..599 growing
                float v = rv[u * kF]; s += v; ss = __fmaf_rn(v, v, ss);
                n += 1.0f;
                float inv = __fdividef(1.0f, n);
                float m   = s * inv;
                float var = __fmaf_rn(-m, m, ss * inv);
                __stcs(po + u * kF, (v - m) * rsqrtf(var));
            }
            mean = s * kInvW; qss = ss * kInvW;
            #pragma unroll
            for (int u = 8; u < 16; ++u) {         // rows 600..607 steady-1
                float vn = rv[u * kF];
                float vo = (u == 8) ? 0.0f : ring[(u - 9) * kF + f];
                float t1 = (vn - vo) * kInvW;
                mean += t1;
                qss   = __fmaf_rn(t1, vn + vo, qss);
                float var = __fmaf_rn(-mean, mean, qss);
                __stcs(po + u * kF, (vn - mean) * rsqrtf(var));
            }
            vnF += 16 * kF; issue16();             // vnF = 608*kF
        }
        g0row   = 608;
        nSteady = (kL - 608) / 16;                 // 379
    } else {
        // warmup group 0: rows t0+7 .. t0+15 (start-601 .. start-593)
        {
            cpwait2(); __syncthreads();
            const float* rv = ring + vnF + f;
            #pragma unroll
            for (int u = 7; u < 16; ++u) {
                float v = rv[u * kF]; s += v; ss = __fmaf_rn(v, v, ss);
            }
            vnF += 16 * kF; if (vnF == kRLf) vnF = 0;
            issue16();
        }
        // warmup groups 1..37: 592 rows
        #pragma unroll 1
        for (int g = 1; g < 38; ++g) {
            cpwait2(); __syncthreads();
            const float* rv = ring + vnF + f;
            #pragma unroll
            for (int u = 0; u < 16; ++u) {
                float v = rv[u * kF]; s += v; ss = __fmaf_rn(v, v, ss);
            }
            vnF += 16 * kF; if (vnF == kRLf) vnF = 0;
            issue16();
        }
        mean = s * kInvW; qss = ss * kInvW;
        g0row   = start;
        nSteady = (end - start) / 16;              // 417 or 414
    }

    // ---- steady sliding loop with TMA-bulk-store staging ----
    float* poFl = out + (size_t)b * kT * kF + (size_t)g0row * kF; // flush dst
    #pragma unroll 1
    for (int g = 0; g < nSteady; ++g) {
        cpwait2();
        if (f == 0) bulk_waitread0();              // stage buffers free
        __syncthreads();                           // ring + staging visible
        if (f == 0 && g > 0) {                     // flush staged group g-1
            bulk_store(poFl, stb + (uint32_t)(((g - 1) & 1) * kStageF * 4));
            bulk_commit();
            poFl += 16 * kF;
        }
        float* sb = stage + (g & 1) * kStageF;
        int voF = vnF + kVO * kF; if (voF >= kRLf) voF -= kRLf;
        const float* rvn = ring + vnF + f;
        const float* rvo = ring + voF + f;         // mirror covers straddle
        #pragma unroll
        for (int u = 0; u < 16; ++u) {
            float vn = rvn[u * kF];
            float vo = rvo[u * kF];
            float t1 = (vn - vo) * kInvW;
            mean += t1;
            qss   = __fmaf_rn(t1, vn + vo, qss);
            float var = __fmaf_rn(-mean, mean, qss);
            sb[u * kF + f] = (vn - mean) * rsqrtf(var);
        }
        fence_pa();                                // order STS -> async proxy
        vnF += 16 * kF; if (vnF == kRLf) vnF = 0;
        issue16();
    }
    // epilogue: flush last staged group
    __syncthreads();
    if (f == 0) {
        bulk_store(poFl, stb + (uint32_t)(((nSteady - 1) & 1) * kStageF * 4));
        bulk_commit();
        bulk_waitread0();
    }
}

extern "C" void kernel_launch(void* const* d_in, const int* in_sizes, int n_in,
                              void* d_out, int out_size)
{
    const float* x = (const float*)d_in[0];
    float* o = (float*)d_out;
    (void)in_sizes; (void)n_in; (void)out_size;

    cudaFuncSetAttribute(cmn_kernel,
                         cudaFuncAttributeMaxDynamicSharedMemorySize, (int)kSmemB);
    cmn_kernel<<<kGrid, kF, kSmemB>>>(x, o);
}

// round 9
// speedup vs baseline: 1.4247x; 1.4247x over previous
#include <cuda_runtime.h>
#include <cstdint>

// SlidingWindowCmn (16, 60000, 80) fp32, window=600, min=100, center=False,
// norm_vars=True.
// Distributed 16B cp.async -> 672-row SMEM ring (+8 mirror) -> per-thread
// sliding window (1 thread/feature). Outputs staged in SMEM and flushed by
// TMA bulk stores, double-buffered with wait_group.read 1 so the flush of
// group g-1 overlaps compute of group g (R8 bug: wait_group.read 0
// serialized every group behind a full TMA round-trip).
// Lead = 3 groups: cross-thread overwrite safety 16*3 + 15 <= 671-601.

namespace {
constexpr int kB      = 16;
constexpr int kT      = 60000;
constexpr int kF      = 80;
constexpr int kWin    = 600;
constexpr int kMin    = 100;
constexpr int kChunks = 9;
constexpr int kL      = 6672;                 // 8*6672 + 6624 = 60000
constexpr int kRL     = 672;                  // logical ring rows
constexpr int kRLf    = kRL * kF;             // 53760 floats
constexpr uint32_t kRLb = kRL * 320u;         // 215040 bytes (logical)
constexpr int kMirF   = 8 * kF;               // 8 mirror rows
constexpr int kStageF = 16 * kF;              // 1280 floats per stage buffer
constexpr int kRingTotF = kRLf + kMirF;       // 54400 floats
constexpr uint32_t kSmemB = (uint32_t)(kRingTotF + 2 * kStageF) * 4u; // 227840
constexpr int kVO     = kRL - kWin - 1;       // 71 rows vn->vo distance
constexpr float kInvW = 1.0f / 601.0f;
constexpr int kGrid   = kB * kChunks;         // 144
}

__device__ __forceinline__ uint32_t smem_u32(const void* p) {
    uint32_t a;
    asm("{ .reg .u64 t; cvta.to.shared.u64 t, %1; cvt.u32.u64 %0, t; }"
        : "=r"(a) : "l"(p));
    return a;
}
__device__ __forceinline__ void cpa16(uint32_t s, const float* g) {
    asm volatile("cp.async.cg.shared.global [%0], [%1], 16;" :: "r"(s), "l"(g));
}
__device__ __forceinline__ void cpcommit() {
    asm volatile("cp.async.commit_group;" ::: "memory");
}
__device__ __forceinline__ void cpwait2() {
    asm volatile("cp.async.wait_group 2;" ::: "memory");
}
__device__ __forceinline__ void fence_pa() {
    asm volatile("fence.proxy.async.shared::cta;" ::: "memory");
}
__device__ __forceinline__ void bulk_store(float* g, uint32_t s) {
    asm volatile("cp.async.bulk.global.shared::cta.bulk_group [%0], [%1], %2;"
                 :: "l"(g), "r"(s), "r"(5120) : "memory");
}
__device__ __forceinline__ void bulk_commit() {
    asm volatile("cp.async.bulk.commit_group;" ::: "memory");
}
__device__ __forceinline__ void bulk_waitread1() {
    asm volatile("cp.async.bulk.wait_group.read 1;" ::: "memory");
}
__device__ __forceinline__ void bulk_waitread0() {
    asm volatile("cp.async.bulk.wait_group.read 0;" ::: "memory");
}

__global__ void __launch_bounds__(kF, 1)
cmn_kernel(const float* __restrict__ x, float* __restrict__ out)
{
    extern __shared__ float smem[];
    float* ring  = smem;
    float* stage = smem + kRingTotF;

    const int f = threadIdx.x;                    // feature 0..79
    const int c = blockIdx.x % kChunks;
    const int b = blockIdx.x / kChunks;

    const float* xb = x + (size_t)b * kT * kF;
    const int start = c * kL;
    const int end   = (c == kChunks - 1) ? kT : start + kL;

    const uint32_t rsb = smem_u32(ring);
    const uint32_t stb = smem_u32(stage);
    const float* pClamp = x + ((size_t)kB * kT - 16) * kF;

    int vnF;                  // consume group float-offset (slot*80)
    uint32_t issB;            // issue group byte-offset
    const float* pIss;
    if (c == 0) {
        vnF = 0; issB = 0; pIss = xb;
    } else {
        const int t0   = start - 608;             // 16-aligned: 7 pad + 601 warmup
        const int slot = t0 % kRL;                // multiple of 16
        vnF = slot * kF; issB = (uint32_t)slot * 320u;
        pIss = xb + (size_t)t0 * kF;
    }

    auto issue16 = [&]() {
        const float* q  = (pIss > pClamp) ? pClamp : pIss;
        const float* qt = q + f * 4;                         // 16B per thread
        const uint32_t a = rsb + issB + (uint32_t)(f << 4);
        cpa16(a,         qt);
        cpa16(a + 1280u, qt + 320);
        cpa16(a + 2560u, qt + 640);
        cpa16(a + 3840u, qt + 960);
        if (issB == 0) {                          // wrap group: mirror rows 0..7
            const uint32_t m = rsb + kRLb + (uint32_t)(f << 4);
            cpa16(m,         qt);
            cpa16(m + 1280u, qt + 320);
        }
        cpcommit();
        pIss += 16 * kF;
        issB += 5120u; if (issB == kRLb) issB = 0;
    };

    // prologue: 3 groups (48 rows) in flight
    issue16(); issue16(); issue16();

    float s = 0.f, ss = 0.f, mean = 0.f, qss = 0.f;
    float* po = out + (size_t)b * kT * kF + f;
    int nSteady, g0row;

    if (c == 0) {
        // groups 0..5: rows 0..95 accumulate
        #pragma unroll 1
        for (int g = 0; g < 6; ++g) {
            cpwait2(); __syncthreads();
            const float* rv = ring + vnF + f;
            #pragma unroll
            for (int u = 0; u < 16; ++u) {
                float v = rv[u * kF]; s += v; ss = __fmaf_rn(v, v, ss);
            }
            vnF += 16 * kF; issue16();
        }
        // group 6: rows 96..111
        {
            cpwait2(); __syncthreads();
            const float* rv = ring + vnF + f;
            #pragma unroll
            for (int u = 0; u < 4; ++u) {          // rows 96..99
                float v = rv[u * kF]; s += v; ss = __fmaf_rn(v, v, ss);
            }
            const float inv = 1.0f / (float)kMin;  // burst rows 0..99
            const float m0  = s * inv;
            const float vr0 = __fmaf_rn(-m0, m0, ss * inv);
            const float rs0 = rsqrtf(vr0);
            #pragma unroll 4
            for (int t = 0; t < kMin; ++t) {
                float v = ring[t * kF + f];
                __stcs(po + t * kF, (v - m0) * rs0);
            }
            float n = 100.0f;
            #pragma unroll
            for (int u = 4; u < 16; ++u) {         // rows 100..111 growing
                float v = rv[u * kF]; s += v; ss = __fmaf_rn(v, v, ss);
                n += 1.0f;
                float inv2 = __fdividef(1.0f, n);
                float m    = s * inv2;
                float var  = __fmaf_rn(-m, m, ss * inv2);
                __stcs(po + (96 + u) * kF, (v - m) * rsqrtf(var));
            }
            vnF += 16 * kF; issue16();
        }
        // groups 7..36: rows 112..591 growing
        po += 112 * kF;
        float n = 112.0f;
        #pragma unroll 1
        for (int g = 7; g < 37; ++g) {
            cpwait2(); __syncthreads();
            const float* rv = ring + vnF + f;
            #pragma unroll
            for (int u = 0; u < 16; ++u) {
                float v = rv[u * kF]; s += v; ss = __fmaf_rn(v, v, ss);
                n += 1.0f;
                float inv = __fdividef(1.0f, n);
                float m   = s * inv;
                float var = __fmaf_rn(-m, m, ss * inv);
                __stcs(po + u * kF, (v - m) * rsqrtf(var));
            }
            vnF += 16 * kF; po += 16 * kF; issue16();
        }
        // group 37: rows 592..607 (transition at t=600)
        {
            cpwait2(); __syncthreads();
            const float* rv = ring + vnF + f;
            #pragma unroll
            for (int u = 0; u < 8; ++u) {          // rows 592..599 growing
                float v = rv[u * kF]; s += v; ss = __fmaf_rn(v, v, ss);
                n += 1.0f;
                float inv = __fdividef(1.0f, n);
                float m   = s * inv;
                float var = __fmaf_rn(-m, m, ss * inv);
                __stcs(po + u * kF, (v - m) * rsqrtf(var));
            }
            mean = s * kInvW; qss = ss * kInvW;
            #pragma unroll
            for (int u = 8; u < 16; ++u) {         // rows 600..607 steady-1
                float vn = rv[u * kF];
                float vo = (u == 8) ? 0.0f : ring[(u - 9) * kF + f];
                float t1 = (vn - vo) * kInvW;
                mean += t1;
                qss   = __fmaf_rn(t1, vn + vo, qss);
                float var = __fmaf_rn(-mean, mean, qss);
                __stcs(po + u * kF, (vn - mean) * rsqrtf(var));
            }
            vnF += 16 * kF; issue16();             // vnF = 608*kF
        }
        g0row   = 608;
        nSteady = (kL - 608) / 16;                 // 379
    } else {
        // warmup group 0: rows t0+7 .. t0+15 (start-601 .. start-593)
        {
            cpwait2(); __syncthreads();
            const float* rv = ring + vnF + f;
            #pragma unroll
            for (int u = 7; u < 16; ++u) {
                float v = rv[u * kF]; s += v; ss = __fmaf_rn(v, v, ss);
            }
            vnF += 16 * kF; if (vnF == kRLf) vnF = 0;
            issue16();
        }
        // warmup groups 1..37: 592 rows
        #pragma unroll 1
        for (int g = 1; g < 38; ++g) {
            cpwait2(); __syncthreads();
            const float* rv = ring + vnF + f;
            #pragma unroll
            for (int u = 0; u < 16; ++u) {
                float v = rv[u * kF]; s += v; ss = __fmaf_rn(v, v, ss);
            }
            vnF += 16 * kF; if (vnF == kRLf) vnF = 0;
            issue16();
        }
        mean = s * kInvW; qss = ss * kInvW;
        g0row   = start;
        nSteady = (end - start) / 16;              // 417 or 414
    }

    // ---- steady sliding loop, TMA-bulk stores double-buffered ----
    float* poFl = out + (size_t)b * kT * kF + (size_t)g0row * kF; // flush dst
    #pragma unroll 1
    for (int g = 0; g < nSteady; ++g) {
        cpwait2();
        __syncthreads();                 // ring ready; stage(g-1) STS visible
        if (f == 0 && g > 0) {
            bulk_store(poFl, stb + (uint32_t)(((g - 1) & 1) * kStageF * 4));
            bulk_commit();               // store(g-1) in flight
            bulk_waitread1();            // store(g-2) has finished reading
            poFl += 16 * kF;
        }
        __syncthreads();                 // buffer (g&1) free for all threads
        float* sb = stage + (g & 1) * kStageF;
        int voF = vnF + kVO * kF; if (voF >= kRLf) voF -= kRLf;
        const float* rvn = ring + vnF + f;
        const float* rvo = ring + voF + f;          // mirror covers straddle
        #pragma unroll
        for (int u = 0; u < 16; ++u) {
            float vn = rvn[u * kF];
            float vo = rvo[u * kF];
            float t1 = (vn - vo) * kInvW;
            mean += t1;
            qss   = __fmaf_rn(t1, vn + vo, qss);
            float var = __fmaf_rn(-mean, mean, qss);
            sb[u * kF + f] = (vn - mean) * rsqrtf(var);
        }
        fence_pa();                      // order this thread's STS -> async proxy
        vnF += 16 * kF; if (vnF == kRLf) vnF = 0;
        issue16();
    }
    // epilogue: flush last staged group
    __syncthreads();
    if (f == 0) {
        bulk_store(poFl, stb + (uint32_t)(((nSteady - 1) & 1) * kStageF * 4));
        bulk_commit();
        bulk_waitread0();
    }
}

extern "C" void kernel_launch(void* const* d_in, const int* in_sizes, int n_in,
                              void* d_out, int out_size)
{
    const float* x = (const float*)d_in[0];
    float* o = (float*)d_out;
    (void)in_sizes; (void)n_in; (void)out_size;

    cudaFuncSetAttribute(cmn_kernel,
                         cudaFuncAttributeMaxDynamicSharedMemorySize, (int)kSmemB);
    cmn_kernel<<<kGrid, kF, kSmemB>>>(x, o);
}

// round 10
// speedup vs baseline: 4.7208x; 3.3136x over previous
#include <cuda_runtime.h>
#include <cstdint>

// SlidingWindowCmn (16, 60000, 80) fp32, window=600, min=100, center=False,
// norm_vars=True.
// Feature-split: each (batch, chunk) runs TWO CTAs, each owning 40 of the 80
// features (160 B/row). Ring = 704 rows x 160 B (+8 mirror) = 113920 B ->
// 2 CTAs/SM, doubling latency hiding with zero duplicated traffic.
// Distributed 16B cp.async, 16-row groups, wait_group 4 + __syncthreads,
// lead = 5 groups (overwrite safety: 16*5 + 15 <= 704-601 - 1 per R6 proof).

namespace {
constexpr int kB      = 16;
constexpr int kT      = 60000;
constexpr int kF      = 80;               // global features per row
constexpr int kFH     = 40;               // features per CTA
constexpr int kWin    = 600;
constexpr int kMin    = 100;
constexpr int kChunks = 9;
constexpr int kL      = 6672;             // 8*6672 + 6624 = 60000
constexpr int kRL     = 704;              // logical ring rows
constexpr int kRLf    = kRL * kFH;        // 28160 floats
constexpr uint32_t kRLb = kRL * 160u;     // 112640 bytes (logical)
constexpr uint32_t kSmemB = (kRL + 8) * 160u;  // 113920 bytes (+ mirror)
constexpr int kVO     = kRL - kWin - 1;   // 103 rows vn->vo slot distance
constexpr float kInvW = 1.0f / 601.0f;
constexpr int kGrid   = kB * kChunks * 2; // 288 CTAs
}

__device__ __forceinline__ uint32_t smem_u32(const void* p) {
    uint32_t a;
    asm("{ .reg .u64 t; cvta.to.shared.u64 t, %1; cvt.u32.u64 %0, t; }"
        : "=r"(a) : "l"(p));
    return a;
}
__device__ __forceinline__ void cpa16(uint32_t s, const float* g) {
    asm volatile("cp.async.cg.shared.global [%0], [%1], 16;" :: "r"(s), "l"(g));
}
__device__ __forceinline__ void cpcommit() {
    asm volatile("cp.async.commit_group;" ::: "memory");
}
__device__ __forceinline__ void cpwait4() {
    asm volatile("cp.async.wait_group 4;" ::: "memory");
}

__global__ void __launch_bounds__(kFH, 2)
cmn_kernel(const float* __restrict__ x, float* __restrict__ out)
{
    extern __shared__ float ring[];
    const int tid  = threadIdx.x;                 // 0..39, owns one feature
    const int half = blockIdx.x & 1;              // feature half 0/1
    const int bc   = blockIdx.x >> 1;
    const int c    = bc % kChunks;
    const int b    = bc / kChunks;

    const float* xb = x + (size_t)b * kT * kF;    // batch base (full rows)
    const int start = c * kL;
    const int end   = (c == kChunks - 1) ? kT : start + kL;

    const uint32_t rsb = smem_u32(ring);
    const float* pClamp = x + ((size_t)kB * kT - 16) * kF;  // last full group

    // cp.async per-thread source offset within a 4-row block of this half:
    // row (tid/10), bytes (tid%10)*16 of the 160B half-row.
    const int thrOffG = (tid / 10) * kF + half * kFH + (tid % 10) * 4;

    int vnF;                  // consume group float-offset (slot*40)
    uint32_t issB;            // issue group byte-offset
    const float* pIss;        // group base (global floats, full-row units)
    if (c == 0) {
        vnF = 0; issB = 0; pIss = xb;
    } else {
        const int t0   = start - 608;             // 16-aligned: 7 pad + 601 warmup
        const int slot = t0 % kRL;                // multiple of 16
        vnF = slot * kFH; issB = (uint32_t)slot * 160u;
        pIss = xb + (size_t)t0 * kF;
    }

    auto issue16 = [&]() {
        const float* q  = (pIss > pClamp) ? pClamp : pIss;
        const float* qt = q + thrOffG;                      // 16B per thread
        const uint32_t a = rsb + issB + (uint32_t)(tid << 4);
        cpa16(a,         qt);            // rows +0..3
        cpa16(a +  640u, qt + 4 * kF);   // rows +4..7
        cpa16(a + 1280u, qt + 8 * kF);   // rows +8..11
        cpa16(a + 1920u, qt + 12 * kF);  // rows +12..15
        if (issB == 0) {                 // wrap group: mirror rows 0..7
            const uint32_t m = rsb + kRLb + (uint32_t)(tid << 4);
            cpa16(m,        qt);
            cpa16(m + 640u, qt + 4 * kF);
        }
        cpcommit();
        pIss += 16 * kF;
        issB += 2560u; if (issB == kRLb) issB = 0;
    };

    // prologue: 5 groups (80 rows) in flight
    #pragma unroll 1
    for (int g = 0; g < 5; ++g) issue16();

    float s = 0.f, ss = 0.f, mean = 0.f, qss = 0.f;
    float* po = out + (size_t)b * kT * kF + half * kFH + tid;
    int nSteady, g0row;

    if (c == 0) {
        // groups 0..5: rows 0..95 accumulate
        #pragma unroll 1
        for (int g = 0; g < 6; ++g) {
            cpwait4(); __syncthreads();
            const float* rv = ring + vnF + tid;
            #pragma unroll
            for (int u = 0; u < 16; ++u) {
                float v = rv[u * kFH]; s += v; ss = __fmaf_rn(v, v, ss);
            }
            vnF += 16 * kFH; issue16();
        }
        // group 6: rows 96..111
        {
            cpwait4(); __syncthreads();
            const float* rv = ring + vnF + tid;
            #pragma unroll
            for (int u = 0; u < 4; ++u) {          // rows 96..99
                float v = rv[u * kFH]; s += v; ss = __fmaf_rn(v, v, ss);
            }
            const float inv = 1.0f / (float)kMin;  // burst rows 0..99
            const float m0  = s * inv;
            const float vr0 = __fmaf_rn(-m0, m0, ss * inv);
            const float rs0 = rsqrtf(vr0);
            #pragma unroll 4
            for (int t = 0; t < kMin; ++t) {
                float v = ring[t * kFH + tid];
                __stcs(po + t * kF, (v - m0) * rs0);
            }
            float n = 100.0f;
            #pragma unroll
            for (int u = 4; u < 16; ++u) {         // rows 100..111 growing
                float v = rv[u * kFH]; s += v; ss = __fmaf_rn(v, v, ss);
                n += 1.0f;
                float inv2 = __fdividef(1.0f, n);
                float m    = s * inv2;
                float var  = __fmaf_rn(-m, m, ss * inv2);
                __stcs(po + (96 + u) * kF, (v - m) * rsqrtf(var));
            }
            vnF += 16 * kFH; issue16();
        }
        // groups 7..36: rows 112..591 growing
        po += 112 * kF;
        float n = 112.0f;
        #pragma unroll 1
        for (int g = 7; g < 37; ++g) {
            cpwait4(); __syncthreads();
            const float* rv = ring + vnF + tid;
            #pragma unroll
            for (int u = 0; u < 16; ++u) {
                float v = rv[u * kFH]; s += v; ss = __fmaf_rn(v, v, ss);
                n += 1.0f;
                float inv = __fdividef(1.0f, n);
                float m   = s * inv;
                float var = __fmaf_rn(-m, m, ss * inv);
                __stcs(po + u * kF, (v - m) * rsqrtf(var));
            }
            vnF += 16 * kFH; po += 16 * kF; issue16();
        }
        // group 37: rows 592..607 (transition at t=600)
        {
            cpwait4(); __syncthreads();
            const float* rv = ring + vnF + tid;
            #pragma unroll
            for (int u = 0; u < 8; ++u) {          // rows 592..599 growing
                float v = rv[u * kFH]; s += v; ss = __fmaf_rn(v, v, ss);
                n += 1.0f;
                float inv = __fdividef(1.0f, n);
                float m   = s * inv;
                float var = __fmaf_rn(-m, m, ss * inv);
                __stcs(po + u * kF, (v - m) * rsqrtf(var));
            }
            mean = s * kInvW; qss = ss * kInvW;
            #pragma unroll
            for (int u = 8; u < 16; ++u) {         // rows 600..607 steady-1
                float vn = rv[u * kFH];
                float vo = (u == 8) ? 0.0f : ring[(u - 9) * kFH + tid];
                float t1 = (vn - vo) * kInvW;
                mean += t1;
                qss   = __fmaf_rn(t1, vn + vo, qss);
                float var = __fmaf_rn(-mean, mean, qss);
                __stcs(po + u * kF, (vn - mean) * rsqrtf(var));
            }
            vnF += 16 * kFH; issue16();            // vnF = 608*kFH
        }
        g0row   = 608;
        nSteady = (kL - 608) / 16;                 // 379
    } else {
        // warmup group 0: rows t0+7 .. t0+15 (start-601 .. start-593)
        {
            cpwait4(); __syncthreads();
            const float* rv = ring + vnF + tid;
            #pragma unroll
            for (int u = 7; u < 16; ++u) {
                float v = rv[u * kFH]; s += v; ss = __fmaf_rn(v, v, ss);
            }
            vnF += 16 * kFH; if (vnF == kRLf) vnF = 0;
            issue16();
        }
        // warmup groups 1..37: 592 rows
        #pragma unroll 1
        for (int g = 1; g < 38; ++g) {
            cpwait4(); __syncthreads();
            const float* rv = ring + vnF + tid;
            #pragma unroll
            for (int u = 0; u < 16; ++u) {
                float v = rv[u * kFH]; s += v; ss = __fmaf_rn(v, v, ss);
            }
            vnF += 16 * kFH; if (vnF == kRLf) vnF = 0;
            issue16();
        }
        mean = s * kInvW; qss = ss * kInvW;
        g0row   = start;
        nSteady = (end - start) / 16;              // 417 or 414
    }

    // ---- steady sliding loop ----
    float* po2 = out + (size_t)b * kT * kF + (size_t)g0row * kF
               + half * kFH + tid;
    #pragma unroll 1
    for (int g = 0; g < nSteady; ++g) {
        cpwait4(); __syncthreads();
        const float* rvn = ring + vnF + tid;
        int voF = vnF + kVO * kFH;                 // slot (t-601), group-aligned
        if (voF >= kRLf) voF -= kRLf;              // one wrap check / 16 rows
        const float* rvo = ring + voF + tid;       // mirror covers straddle
        #pragma unroll
        for (int u = 0; u < 16; ++u) {
            float vn = rvn[u * kFH];
            float vo = rvo[u * kFH];
            float t1 = (vn - vo) * kInvW;
            mean += t1;
            qss   = __fmaf_rn(t1, vn + vo, qss);
            float var = __fmaf_rn(-mean, mean, qss);
            __stcs(po2 + u * kF, (vn - mean) * rsqrtf(var));
        }
        vnF += 16 * kFH; if (vnF == kRLf) vnF = 0;
        po2 += 16 * kF;
        issue16();
    }
}

extern "C" void kernel_launch(void* const* d_in, const int* in_sizes, int n_in,
                              void* d_out, int out_size)
{
    const float* x = (const float*)d_in[0];
    float* o = (float*)d_out;
    (void)in_sizes; (void)n_in; (void)out_size;

    cudaFuncSetAttribute(cmn_kernel,
                         cudaFuncAttributeMaxDynamicSharedMemorySize, (int)kSmemB);
    cmn_kernel<<<kGrid, kFH, kSmemB>>>(x, o);
}